// round 14
// baseline (speedup 1.0000x reference)
#include <cuda_runtime.h>
#include <cuda_fp16.h>
#include <cstdint>

#define NB     8
#define NLAT   721
#define NLON   1440
#define NCELL  (NLAT * NLON)
#define NJC    (NLAT - 1)            // 720 interp rows (j clipped to <= 719)
#define NQCELL (NJC * NLON)

// Quad-cell field: g_quad[j][i] is a 64B cell = 4 chunks of 16B.
// Chunk r holds batches (2r, 2r+1) for all 4 corners as 4 half2:
//   { v00, v10, v01, v11 }  (v10/v11 are column i+1 with lon-wrap pre-applied)
// 720*1440*64B = 66 MB; written by build -> dirty-resident in L2 for interp.
__device__ uint4 g_quad[(size_t)NQCELL * 4];

__global__ void __launch_bounds__(256) build_kernel(const float* __restrict__ x) {
    int idx = blockIdx.x * blockDim.x + threadIdx.x;   // cell = j*NLON + i
    if (idx >= NQCELL) return;
    int j = idx / NLON;
    int i = idx - j * NLON;
    int i1 = (i + 1 == NLON) ? 0 : i + 1;

    int c00 = j * NLON + i;
    int c10 = j * NLON + i1;
    int c01 = c00 + NLON;
    int c11 = c10 + NLON;

#pragma unroll
    for (int r = 0; r < 4; r++) {
        size_t b0 = (size_t)(2 * r) * NCELL;
        size_t b1 = (size_t)(2 * r + 1) * NCELL;
        __half2 h[4];
        h[0] = __floats2half2_rn(__ldg(&x[b0 + c00]), __ldg(&x[b1 + c00]));
        h[1] = __floats2half2_rn(__ldg(&x[b0 + c10]), __ldg(&x[b1 + c10]));
        h[2] = __floats2half2_rn(__ldg(&x[b0 + c01]), __ldg(&x[b1 + c01]));
        h[3] = __floats2half2_rn(__ldg(&x[b0 + c11]), __ldg(&x[b1 + c11]));
        g_quad[(size_t)idx * 4 + r] = *reinterpret_cast<uint4*>(h);
    }
}

// 4 lanes per point. Lane r loads the 16B chunk for its 2 batches (all four
// lanes hit the same 64B-aligned cell -> ~1 L1 wavefront per point), computes
// the full bilinear locally (no shuffles), writes a coalesced float2.
__global__ void __launch_bounds__(256) interp_kernel(const float2* __restrict__ xi,
                                                     float* __restrict__ out,
                                                     int n) {
    int t = blockIdx.x * blockDim.x + threadIdx.x;
    int p = t >> 2;
    if (p >= n) return;
    int r = t & 3;

    float2 q = __ldcs(&xi[p]);

    // Uniform 0.25-degree grids: searchsorted == floor(coord * 4) (exact *2^2)
    int i = (int)floorf(q.x * 4.0f);
    i = max(0, min(i, NLON - 1));
    float wlon = (q.x - 0.25f * (float)i) * 4.0f;

    int j = (int)floorf((q.y + 90.0f) * 4.0f);
    j = max(0, min(j, NLAT - 2));
    float wlat = (q.y - fmaf(0.25f, (float)j, -90.0f)) * 4.0f;

    uint4 c = __ldg(&g_quad[((size_t)j * NLON + i) * 4 + r]);
    const __half2* hp = reinterpret_cast<const __half2*>(&c);
    float2 f00 = __half22float2(hp[0]);
    float2 f10 = __half22float2(hp[1]);
    float2 f01 = __half22float2(hp[2]);
    float2 f11 = __half22float2(hp[3]);

    float ol = 1.0f - wlon, oa = 1.0f - wlat;
    float w00 = ol * oa, w10 = wlon * oa, w01 = ol * wlat, w11 = wlon * wlat;

    float2 o;
    o.x = w00 * f00.x + w10 * f10.x + w01 * f01.x + w11 * f11.x;
    o.y = w00 * f00.y + w10 * f10.y + w01 * f01.y + w11 * f11.y;

    // out is [N, B]: lane r writes batches (2r, 2r+1) -> fully coalesced 8B stores
    __stcs(reinterpret_cast<float2*>(out + (size_t)p * NB + 2 * r), o);
}

extern "C" void kernel_launch(void* const* d_in, const int* in_sizes, int n_in,
                              void* d_out, int out_size) {
    const float* x   = (const float*)d_in[0];   // [B, NLAT, NLON]
    const float2* xi = (const float2*)d_in[3];  // [N, 2]
    float* out = (float*)d_out;                 // [N, B]

    int n = in_sizes[3] / 2;

    build_kernel<<<(NQCELL + 255) / 256, 256>>>(x);
    int threads = 4 * n;
    interp_kernel<<<(threads + 255) / 256, 256>>>(xi, out, n);
}

// round 15
// speedup vs baseline: 1.2584x; 1.2584x over previous
#include <cuda_runtime.h>
#include <cuda_fp16.h>
#include <cstdint>

#define NB     8
#define NLAT   721
#define NLON   1440
#define NCELL  (NLAT * NLON)
#define NJC    (NLAT - 1)            // 720 cell rows (j clipped to <= 719)
#define NQCELL (NJC * NLON)

// Vertical-pair cells: g_cell[j*NLON+i] is 32B = 2 chunks of 16B:
//   chunk0 = row j,   batches 0..7 (fp16)
//   chunk1 = row j+1, batches 0..7
// 720*1440*32B = 33 MB -> L2-resident (validated at this footprint in R2).
__device__ uint4 g_cell[(size_t)NQCELL * 2];

__global__ void __launch_bounds__(256) build_kernel(const float* __restrict__ x) {
    int idx = blockIdx.x * blockDim.x + threadIdx.x;   // cell = j*NLON + i
    if (idx >= NQCELL) return;
    // rows j and j+1 at column i; idx == j*NLON + i also indexes x's [nlat,nlon] plane
#pragma unroll
    for (int row = 0; row < 2; row++) {
        int c = idx + row * NLON;
        __half2 h[4];
#pragma unroll
        for (int b = 0; b < 4; b++) {
            float lo = __ldg(&x[(size_t)(2 * b)     * NCELL + c]);
            float hi = __ldg(&x[(size_t)(2 * b + 1) * NCELL + c]);
            h[b] = __floats2half2_rn(lo, hi);
        }
        g_cell[(size_t)idx * 2 + row] = *reinterpret_cast<uint4*>(h);
    }
}

// 4 lanes per point. Lane r owns corner (row = r&1, col = (r&2)? i1 : i) and
// loads ONE uint4; the quad's 4 loads cover a contiguous 64B region (~1.25
// cache lines). Butterfly: xor1 combines rows, 2-slot xor2 combines columns.
__global__ void __launch_bounds__(256) interp_kernel(const float2* __restrict__ xi,
                                                     float* __restrict__ out,
                                                     int n) {
    int t = blockIdx.x * blockDim.x + threadIdx.x;
    int p = t >> 2;
    if (p >= n) return;
    int r = t & 3;
    bool odd = (r & 1) != 0;   // row bit
    bool hi  = (r & 2) != 0;   // col bit

    float2 q = __ldcs(&xi[p]);

    // Uniform 0.25-degree grids: searchsorted == floor(coord * 4) (exact *2^2)
    int i = (int)floorf(q.x * 4.0f);
    i = max(0, min(i, NLON - 1));
    float wlon = (q.x - 0.25f * (float)i) * 4.0f;

    int j = (int)floorf((q.y + 90.0f) * 4.0f);
    j = max(0, min(j, NLAT - 2));
    float wlat = (q.y - fmaf(0.25f, (float)j, -90.0f)) * 4.0f;

    int i1 = (i + 1 == NLON) ? 0 : i + 1;      // periodic wrap
    int col = hi ? i1 : i;

    uint4 c = __ldg(&g_cell[((size_t)j * NLON + col) * 2 + (r & 1)]);

    float wla = odd ? wlat : (1.0f - wlat);
    float wlo = hi  ? wlon : (1.0f - wlon);
    float w = wla * wlo;

    const __half2* hp = reinterpret_cast<const __half2*>(&c);
    float s[8];
#pragma unroll
    for (int k = 0; k < 4; k++) {
        float2 f = __half22float2(hp[k]);
        s[2 * k]     = w * f.x;
        s[2 * k + 1] = w * f.y;
    }

    // Round 1: combine rows (partner differs in bit0) -> column sums, all 8 batches
#pragma unroll
    for (int k = 0; k < 8; k++)
        s[k] += __shfl_xor_sync(0xffffffffu, s[k], 1);

    // Round 2: combine columns, exchanging only the 2 slots each lane writes.
    // keep_base = 2r, send_base = 2r ^ 4.
    float k0  = hi ? (odd ? s[6] : s[4]) : (odd ? s[2] : s[0]);
    float k1  = hi ? (odd ? s[7] : s[5]) : (odd ? s[3] : s[1]);
    float sd0 = hi ? (odd ? s[2] : s[0]) : (odd ? s[6] : s[4]);
    float sd1 = hi ? (odd ? s[3] : s[1]) : (odd ? s[7] : s[5]);

    float2 o;
    o.x = k0 + __shfl_xor_sync(0xffffffffu, sd0, 2);
    o.y = k1 + __shfl_xor_sync(0xffffffffu, sd1, 2);

    // out is [N, B]: thread t writes 8B at byte offset 8*t -> fully coalesced
    __stcs(reinterpret_cast<float2*>(out + (size_t)p * NB + 2 * r), o);
}

extern "C" void kernel_launch(void* const* d_in, const int* in_sizes, int n_in,
                              void* d_out, int out_size) {
    const float* x   = (const float*)d_in[0];   // [B, NLAT, NLON]
    const float2* xi = (const float2*)d_in[3];  // [N, 2]
    float* out = (float*)d_out;                 // [N, B]

    int n = in_sizes[3] / 2;

    build_kernel<<<(NQCELL + 255) / 256, 256>>>(x);
    int threads = 4 * n;
    interp_kernel<<<(threads + 255) / 256, 256>>>(xi, out, n);
}

// round 16
// speedup vs baseline: 1.5834x; 1.2582x over previous
#include <cuda_runtime.h>
#include <cuda_fp16.h>
#include <cstdint>

#define NB     8
#define NLAT   721
#define NLON   1440
#define NCELL  (NLAT * NLON)
#define NJC    (NLAT - 1)            // 720 cell rows (j clipped to <= 719)
#define NQCELL (NJC * NLON)

// Batch-pair-major vertical cells: g_cell[j*NLON+i] is 32B = 2 sub-chunks of 16B.
// Sub-chunk h (one uint4) is SELF-CONTAINED for batches 4h..4h+3:
//   { half2(rowj,   b4h,b4h+1), half2(rowj,   b4h+2,b4h+3),
//     half2(rowj+1, b4h,b4h+1), half2(rowj+1, b4h+2,b4h+3) }
// 720*1440*32B = 33 MB -> L2-resident (validated R2/R15).
__device__ uint4 g_cell[(size_t)NQCELL * 2];

__global__ void __launch_bounds__(256) build_kernel(const float* __restrict__ x) {
    int idx = blockIdx.x * blockDim.x + threadIdx.x;   // cell = j*NLON + i
    if (idx >= NQCELL) return;
    int c0 = idx;          // row j    offset within a [nlat, nlon] plane
    int c1 = idx + NLON;   // row j+1
#pragma unroll
    for (int h = 0; h < 2; h++) {
        float t0 = __ldg(&x[(size_t)(4 * h + 0) * NCELL + c0]);
        float t1 = __ldg(&x[(size_t)(4 * h + 1) * NCELL + c0]);
        float t2 = __ldg(&x[(size_t)(4 * h + 2) * NCELL + c0]);
        float t3 = __ldg(&x[(size_t)(4 * h + 3) * NCELL + c0]);
        float b0 = __ldg(&x[(size_t)(4 * h + 0) * NCELL + c1]);
        float b1 = __ldg(&x[(size_t)(4 * h + 1) * NCELL + c1]);
        float b2 = __ldg(&x[(size_t)(4 * h + 2) * NCELL + c1]);
        float b3 = __ldg(&x[(size_t)(4 * h + 3) * NCELL + c1]);
        __half2 hh[4];
        hh[0] = __floats2half2_rn(t0, t1);
        hh[1] = __floats2half2_rn(t2, t3);
        hh[2] = __floats2half2_rn(b0, b1);
        hh[3] = __floats2half2_rn(b2, b3);
        g_cell[(size_t)idx * 2 + h] = *reinterpret_cast<uint4*>(hh);
    }
}

// 2 lanes per point, lane h owns batches 4h..4h+3. Two LDG.128 (columns i and
// i1) give it all 4 corners for its batches -> full bilinear computed locally,
// no shuffles, coalesced float4 store.
__global__ void __launch_bounds__(256) interp_kernel(const float2* __restrict__ xi,
                                                     float* __restrict__ out,
                                                     int n) {
    int t = blockIdx.x * blockDim.x + threadIdx.x;
    int p = t >> 1;
    if (p >= n) return;
    int h = t & 1;

    float2 q = __ldcs(&xi[p]);

    // Uniform 0.25-degree grids: searchsorted == floor(coord * 4) (exact *2^2)
    int i = __float2int_rd(q.x * 4.0f);
    i = max(0, min(i, NLON - 1));
    float wlon = (q.x - 0.25f * (float)i) * 4.0f;

    int j = __float2int_rd((q.y + 90.0f) * 4.0f);
    j = max(0, min(j, NLAT - 2));
    float wlat = (q.y - fmaf(0.25f, (float)j, -90.0f)) * 4.0f;

    int i1 = (i + 1 == NLON) ? 0 : i + 1;      // periodic wrap

    size_t row = (size_t)j * NLON;
    uint4 ca = __ldg(&g_cell[(row + i ) * 2 + h]);   // col i : all 4 corners' data
    uint4 cb = __ldg(&g_cell[(row + i1) * 2 + h]);   // col i1

    float ol = 1.0f - wlon, oa = 1.0f - wlat;
    float w00 = oa * ol, w10 = oa * wlon, w01 = wlat * ol, w11 = wlat * wlon;

    const __half2* ha = reinterpret_cast<const __half2*>(&ca);
    const __half2* hb = reinterpret_cast<const __half2*>(&cb);
    float2 at0 = __half22float2(ha[0]);   // col i, row j,   batches 4h,4h+1
    float2 at1 = __half22float2(ha[1]);   // col i, row j,   batches 4h+2,4h+3
    float2 ab0 = __half22float2(ha[2]);   // col i, row j+1
    float2 ab1 = __half22float2(ha[3]);
    float2 bt0 = __half22float2(hb[0]);   // col i1, row j
    float2 bt1 = __half22float2(hb[1]);
    float2 bb0 = __half22float2(hb[2]);   // col i1, row j+1
    float2 bb1 = __half22float2(hb[3]);

    float4 o;
    o.x = w00 * at0.x + w10 * bt0.x + w01 * ab0.x + w11 * bb0.x;
    o.y = w00 * at0.y + w10 * bt0.y + w01 * ab0.y + w11 * bb0.y;
    o.z = w00 * at1.x + w10 * bt1.x + w01 * ab1.x + w11 * bb1.x;
    o.w = w00 * at1.y + w10 * bt1.y + w01 * ab1.y + w11 * bb1.y;

    // out is [N, B]: thread t writes 16B at byte offset 16*t -> fully coalesced
    __stcs(reinterpret_cast<float4*>(out + (size_t)p * NB + 4 * h), o);
}

extern "C" void kernel_launch(void* const* d_in, const int* in_sizes, int n_in,
                              void* d_out, int out_size) {
    const float* x   = (const float*)d_in[0];   // [B, NLAT, NLON]
    const float2* xi = (const float2*)d_in[3];  // [N, 2]
    float* out = (float*)d_out;                 // [N, B]

    int n = in_sizes[3] / 2;

    build_kernel<<<(NQCELL + 255) / 256, 256>>>(x);
    int threads = 2 * n;
    interp_kernel<<<(threads + 255) / 256, 256>>>(xi, out, n);
}